// round 4
// baseline (speedup 1.0000x reference)
#include <cuda_runtime.h>
#include <cuda_bf16.h>
#include <math.h>

#define EPS_CLAMP 1e-4f
#define BLK 128
#define CHUNK 32              // items whose output is staged per flush phase
#define NCHUNK (BLK / CHUNK)  // 4

// ---------------------------------------------------------------------------
// One thread per batch element.
//  - Per-block prep (cheap, overlapped with vech loads): M = W3W2W1 [9x3],
//    C9 = EPS*(I9 - M' M'^T terms) [9x9] in smem.
//  - Per-thread: analytic eigenvalues of symmetric 3x3 + Newton divided
//    differences -> exp(A) = alpha*A^2 + beta*A + gamma*I (no eigenvectors).
//  - Output staged through a SMALL (CHUNK*81) smem buffer in NCHUNK phases
//    to keep smem ~11KB -> high occupancy; coalesced float4 stores.
// ---------------------------------------------------------------------------
__global__ void __launch_bounds__(BLK)
spd_main_kernel(const float* __restrict__ vech,
                const float* __restrict__ W1,
                const float* __restrict__ W2,
                const float* __restrict__ W3,
                float* __restrict__ out, int B) {
    __shared__ __align__(16) float stage[CHUNK * 81];  // 10368 B
    __shared__ float A1[25];   // I5 - W1 W1^T
    __shared__ float W21[21];  // W2 @ W1 [7,3]
    __shared__ float S7[49];   // W2 A1 W2^T + (I7 - W2 W2^T)
    __shared__ float sM[27];   // M = W3 W2 W1 [9,3]
    __shared__ float sC[81];   // EPS * (W3 S7 W3^T + I9 - W3 W3^T)
    __shared__ float sV[BLK * 6];  // staged vech

    const int t = threadIdx.x;
    const int item0 = blockIdx.x * BLK;
    const int nItems = min(BLK, B - item0);

    // Stage vech reads coalesced (issue global loads early)
    {
        const int nflt = nItems * 6;
        for (int idx = t; idx < nflt; idx += BLK)
            sV[idx] = vech[(size_t)item0 * 6 + idx];
    }

    // ---- prep phase 0 ----
    if (t < 25) {
        int i = t / 5, j = t % 5;
        float s = 0.f;
        #pragma unroll
        for (int k = 0; k < 3; k++) s += W1[i*3+k] * W1[j*3+k];
        A1[t] = (i == j ? 1.0f : 0.0f) - s;
    } else if (t < 46) {
        int u = t - 25; int i = u / 3, k = u % 3;
        float s = 0.f;
        #pragma unroll
        for (int a = 0; a < 5; a++) s += W2[i*5+a] * W1[a*3+k];
        W21[u] = s;
    }
    __syncthreads();

    // ---- prep phase 1 ----
    if (t < 49) {
        int i = t / 7, j = t % 7;
        float s = 0.f;
        #pragma unroll
        for (int a = 0; a < 5; a++) {
            float ta = 0.f;
            #pragma unroll
            for (int b = 0; b < 5; b++) ta += A1[a*5+b] * W2[j*5+b];
            s += W2[i*5+a] * ta;
        }
        float w2ij = 0.f;
        #pragma unroll
        for (int a = 0; a < 5; a++) w2ij += W2[i*5+a] * W2[j*5+a];
        S7[t] = s + (i == j ? 1.0f : 0.0f) - w2ij;
    } else if (t < 76) {
        int u = t - 49; int r = u / 3, k = u % 3;
        float s = 0.f;
        #pragma unroll
        for (int a = 0; a < 7; a++) s += W3[r*7+a] * W21[a*3+k];
        sM[u] = s;
    }
    __syncthreads();

    // ---- prep phase 2 ----
    if (t < 81) {
        int i = t / 9, j = t % 9;
        float s = 0.f;
        #pragma unroll
        for (int a = 0; a < 7; a++) {
            float ta = 0.f;
            #pragma unroll
            for (int b = 0; b < 7; b++) ta += S7[a*7+b] * W3[j*7+b];
            s += W3[i*7+a] * ta;
        }
        float w3ij = 0.f;
        #pragma unroll
        for (int a = 0; a < 7; a++) w3ij += W3[i*7+a] * W3[j*7+a];
        sC[t] = EPS_CLAMP * (s + (i == j ? 1.0f : 0.0f) - w3ij);
    }
    __syncthreads();  // sM, sC, sV ready

    const bool active = t < nItems;
    float Y[9][3];     // M * exp(A), kept in regs until this thread's flush phase

    if (active) {
        const float a00 = sV[t*6+0], a01 = sV[t*6+1], a02 = sV[t*6+2];
        const float a11 = sV[t*6+3], a12 = sV[t*6+4], a22 = sV[t*6+5];

        // ---- analytic eigenvalues (trig method), l0 >= l1 >= l2 ----
        const float q   = (a00 + a11 + a22) * (1.0f / 3.0f);
        const float b00 = a00 - q, b11 = a11 - q, b22 = a22 - q;
        const float off2 = a01*a01 + a02*a02 + a12*a12;
        const float p2_half = 0.5f * (b00*b00 + b11*b11 + b22*b22) + off2;
        const float pp = sqrtf(p2_half * (1.0f / 3.0f));
        const float detB = b00 * (b11*b22 - a12*a12)
                         - a01 * (a01*b22 - a12*a02)
                         + a02 * (a01*a12 - b11*a02);
        const float pinv = __fdividef(1.0f, fmaxf(pp, 1e-30f));
        float r = 0.5f * detB * pinv * pinv * pinv;
        r = fminf(1.0f, fmaxf(-1.0f, r));
        const float phi = acosf(r) * (1.0f / 3.0f);
        const float l0 = q + 2.0f * pp * __cosf(phi);
        const float l2 = q + 2.0f * pp * __cosf(phi + 2.0943951023931953f);
        const float l1 = 3.0f * q - l0 - l2;

        // ---- exp via Newton divided differences (expm1-stable) ----
        const float d01 = l0 - l1, d12 = l1 - l2, d02 = l0 - l2;
        const float e2  = __expf(l2);
        const float g12 = expm1f(d12);
        const float e1  = e2 * (g12 + 1.0f);
        const float f12 = (d12 > 1e-10f) ? e2 * __fdividef(g12, d12) : e2;
        const float g01 = expm1f(d01);
        const float e0  = e1 * (g01 + 1.0f);
        const float f01 = (d01 > 1e-10f) ? e1 * __fdividef(g01, d01) : e1;
        const float f012 = (d02 > 1e-10f) ? __fdividef(f01 - f12, d02) : 0.5f * e1;

        const float alpha = f012;
        const float beta  = f01 - f012 * (l0 + l1);
        const float gamma = e0 - f01 * l0 + f012 * (l0 * l1);

        // A^2 (symmetric)
        const float s00 = a00*a00 + a01*a01 + a02*a02;
        const float s01 = a00*a01 + a01*a11 + a02*a12;
        const float s02 = a00*a02 + a01*a12 + a02*a22;
        const float s11 = a01*a01 + a11*a11 + a12*a12;
        const float s12 = a01*a02 + a11*a12 + a12*a22;
        const float s22 = a02*a02 + a12*a12 + a22*a22;

        float x[3][3];
        x[0][0] = alpha*s00 + beta*a00 + gamma;
        x[0][1] = alpha*s01 + beta*a01;         x[1][0] = x[0][1];
        x[0][2] = alpha*s02 + beta*a02;         x[2][0] = x[0][2];
        x[1][1] = alpha*s11 + beta*a11 + gamma;
        x[1][2] = alpha*s12 + beta*a12;         x[2][1] = x[1][2];
        x[2][2] = alpha*s22 + beta*a22 + gamma;

        // Y = M * X3   [9,3]
        #pragma unroll
        for (int rr = 0; rr < 9; rr++) {
            const float m0 = sM[rr*3+0], m1 = sM[rr*3+1], m2 = sM[rr*3+2];
            #pragma unroll
            for (int k = 0; k < 3; k++)
                Y[rr][k] = m0 * x[0][k] + m1 * x[1][k] + m2 * x[2][k];
        }
    }
    __syncthreads();  // sV no longer needed; stage about to be reused

    // ---- NCHUNK flush phases: CHUNK items stage -> coalesced global store ----
    #pragma unroll
    for (int c = 0; c < NCHUNK; c++) {
        const int cBase = c * CHUNK;
        const int cItems = min(CHUNK, nItems - cBase);
        if (cItems <= 0) break;

        if (active && (t >> 5) == c) {  // CHUNK==32: chunk == warp
            float* st = &stage[(t & 31) * 81];
            #pragma unroll
            for (int rr = 0; rr < 9; rr++) {
                #pragma unroll
                for (int cc = rr; cc < 9; cc++) {
                    const float val = Y[rr][0] * sM[cc*3+0]
                                    + Y[rr][1] * sM[cc*3+1]
                                    + Y[rr][2] * sM[cc*3+2]
                                    + sC[rr*9+cc];
                    st[rr*9+cc] = val;
                    st[cc*9+rr] = val;
                }
            }
        }
        __syncthreads();

        if (cItems == CHUNK) {
            float4* o4 = reinterpret_cast<float4*>(out + ((size_t)item0 + cBase) * 81);
            const float4* s4 = reinterpret_cast<const float4*>(stage);
            // CHUNK*81/4 = 648 float4 over 128 threads
            #pragma unroll
            for (int idx = t; idx < (CHUNK * 81) / 4; idx += BLK)
                o4[idx] = s4[idx];
        } else {
            const int nOut = cItems * 81;
            float* ob = out + ((size_t)item0 + cBase) * 81;
            for (int idx = t; idx < nOut; idx += BLK)
                ob[idx] = stage[idx];
        }
        __syncthreads();
    }
}

// ---------------------------------------------------------------------------
extern "C" void kernel_launch(void* const* d_in, const int* in_sizes, int n_in,
                              void* d_out, int out_size) {
    const float* vech = nullptr;
    const float* W1 = nullptr;
    const float* W2 = nullptr;
    const float* W3 = nullptr;
    int vech_elems = 0;
    for (int i = 0; i < n_in; i++) {
        int sz = in_sizes[i];
        if (sz == 15)      W1 = (const float*)d_in[i];
        else if (sz == 35) W2 = (const float*)d_in[i];
        else if (sz == 63) W3 = (const float*)d_in[i];
        else { vech = (const float*)d_in[i]; vech_elems = sz; }
    }
    int B = vech_elems / 6;
    int grid = (B + BLK - 1) / BLK;
    spd_main_kernel<<<grid, BLK>>>(vech, W1, W2, W3, (float*)d_out, B);
}

// round 5
// speedup vs baseline: 1.2529x; 1.2529x over previous
#include <cuda_runtime.h>
#include <cuda_bf16.h>
#include <math.h>

#define EPS_CLAMP 1e-4f
#define BLK 128

// ---------------------------------------------------------------------------
// Warp-autonomous SPDNet decoder.
//   prep (block-wide, once): M = W3 W2 W1 [9x3], C9 = EPS*(...) [9x9] in smem.
//   After ONE __syncthreads, each warp independently:
//     - stages its 32 items' vech warp-locally (coalesced), redistributes,
//     - analytic 3x3 eigenvalues + Newton divided differences -> exp(A),
//     - congruence to 9x9 (M in registers), STS to its private stage slice,
//     - coalesced float4 copy slice -> gmem.
//   No block-wide barriers after prep => warp skew doesn't serialize.
// ---------------------------------------------------------------------------
__global__ void __launch_bounds__(BLK)
spd_main_kernel(const float* __restrict__ vech,
                const float* __restrict__ W1,
                const float* __restrict__ W2,
                const float* __restrict__ W3,
                float* __restrict__ out, int B) {
    __shared__ __align__(16) float stage[BLK * 81];  // 4 warp slices of 32*81
    __shared__ float A1[25];   // I5 - W1 W1^T
    __shared__ float W21[21];  // W2 @ W1 [7,3]
    __shared__ float S7[49];   // W2 A1 W2^T + (I7 - W2 W2^T)
    __shared__ float sM[27];   // M = W3 W2 W1 [9,3]
    __shared__ float sC[81];   // EPS * (W3 S7 W3^T + I9 - W3 W3^T)

    const int t    = threadIdx.x;
    const int w    = t >> 5;
    const int lane = t & 31;
    const int item0 = blockIdx.x * BLK;
    const int nItems = min(BLK, B - item0);

    // ---- prep phase 0 ----
    if (t < 25) {
        int i = t / 5, j = t % 5;
        float s = 0.f;
        #pragma unroll
        for (int k = 0; k < 3; k++) s += W1[i*3+k] * W1[j*3+k];
        A1[t] = (i == j ? 1.0f : 0.0f) - s;
    } else if (t < 46) {
        int u = t - 25; int i = u / 3, k = u % 3;
        float s = 0.f;
        #pragma unroll
        for (int a = 0; a < 5; a++) s += W2[i*5+a] * W1[a*3+k];
        W21[u] = s;
    }
    __syncthreads();

    // ---- prep phase 1 ----
    if (t < 49) {
        int i = t / 7, j = t % 7;
        float s = 0.f;
        #pragma unroll
        for (int a = 0; a < 5; a++) {
            float ta = 0.f;
            #pragma unroll
            for (int b = 0; b < 5; b++) ta += A1[a*5+b] * W2[j*5+b];
            s += W2[i*5+a] * ta;
        }
        float w2ij = 0.f;
        #pragma unroll
        for (int a = 0; a < 5; a++) w2ij += W2[i*5+a] * W2[j*5+a];
        S7[t] = s + (i == j ? 1.0f : 0.0f) - w2ij;
    } else if (t < 76) {
        int u = t - 49; int r = u / 3, k = u % 3;
        float s = 0.f;
        #pragma unroll
        for (int a = 0; a < 7; a++) s += W3[r*7+a] * W21[a*3+k];
        sM[u] = s;
    }
    __syncthreads();

    // ---- prep phase 2 ----
    if (t < 81) {
        int i = t / 9, j = t % 9;
        float s = 0.f;
        #pragma unroll
        for (int a = 0; a < 7; a++) {
            float ta = 0.f;
            #pragma unroll
            for (int b = 0; b < 7; b++) ta += S7[a*7+b] * W3[j*7+b];
            s += W3[i*7+a] * ta;
        }
        float w3ij = 0.f;
        #pragma unroll
        for (int a = 0; a < 7; a++) w3ij += W3[i*7+a] * W3[j*7+a];
        sC[t] = EPS_CLAMP * (s + (i == j ? 1.0f : 0.0f) - w3ij);
    }
    __syncthreads();  // ONLY block-wide barrier coupling; warps free after this

    // M into registers (broadcast LDS x27, once)
    float M[27];
    #pragma unroll
    for (int i = 0; i < 27; i++) M[i] = sM[i];

    // ---- warp-local from here on ----
    const int wItem0 = item0 + w * 32;
    const int wn = max(0, min(32, nItems - w * 32));
    float* const slice = &stage[w * 32 * 81];  // 2592 floats, 16B-aligned

    // Stage this warp's vech coalesced into its slice, then redistribute.
    if (wn == 32) {
        #pragma unroll
        for (int k = 0; k < 6; k++)
            slice[k * 32 + lane] = vech[(size_t)wItem0 * 6 + k * 32 + lane];
    } else {
        for (int idx = lane; idx < wn * 6; idx += 32)
            slice[idx] = vech[(size_t)wItem0 * 6 + idx];
    }
    __syncwarp();
    float v[6];
    #pragma unroll
    for (int j = 0; j < 6; j++) v[j] = slice[lane * 6 + j];
    __syncwarp();  // reads done before slice is overwritten with outputs

    const bool active = lane < wn;
    if (active) {
        const float a00 = v[0], a01 = v[1], a02 = v[2];
        const float a11 = v[3], a12 = v[4], a22 = v[5];

        // ---- analytic eigenvalues (trig method), l0 >= l1 >= l2 ----
        const float q   = (a00 + a11 + a22) * (1.0f / 3.0f);
        const float b00 = a00 - q, b11 = a11 - q, b22 = a22 - q;
        const float off2 = a01*a01 + a02*a02 + a12*a12;
        const float p2_half = 0.5f * (b00*b00 + b11*b11 + b22*b22) + off2;
        const float pp = sqrtf(p2_half * (1.0f / 3.0f));
        const float detB = b00 * (b11*b22 - a12*a12)
                         - a01 * (a01*b22 - a12*a02)
                         + a02 * (a01*a12 - b11*a02);
        const float pinv = __fdividef(1.0f, fmaxf(pp, 1e-30f));
        float r = 0.5f * detB * pinv * pinv * pinv;
        r = fminf(1.0f, fmaxf(-1.0f, r));
        const float phi = acosf(r) * (1.0f / 3.0f);
        const float l0 = q + 2.0f * pp * __cosf(phi);
        const float l2 = q + 2.0f * pp * __cosf(phi + 2.0943951023931953f);
        const float l1 = 3.0f * q - l0 - l2;

        // ---- exp via Newton divided differences (expm1-stable) ----
        const float d01 = l0 - l1, d12 = l1 - l2, d02 = l0 - l2;
        const float e2  = __expf(l2);
        const float g12 = expm1f(d12);
        const float e1  = e2 * (g12 + 1.0f);
        const float f12 = (d12 > 1e-10f) ? e2 * __fdividef(g12, d12) : e2;
        const float g01 = expm1f(d01);
        const float e0  = e1 * (g01 + 1.0f);
        const float f01 = (d01 > 1e-10f) ? e1 * __fdividef(g01, d01) : e1;
        const float f012 = (d02 > 1e-10f) ? __fdividef(f01 - f12, d02) : 0.5f * e1;

        const float alpha = f012;
        const float beta  = f01 - f012 * (l0 + l1);
        const float gamma = e0 - f01 * l0 + f012 * (l0 * l1);

        // A^2 (symmetric)
        const float s00 = a00*a00 + a01*a01 + a02*a02;
        const float s01 = a00*a01 + a01*a11 + a02*a12;
        const float s02 = a00*a02 + a01*a12 + a02*a22;
        const float s11 = a01*a01 + a11*a11 + a12*a12;
        const float s12 = a01*a02 + a11*a12 + a12*a22;
        const float s22 = a02*a02 + a12*a12 + a22*a22;

        float x[3][3];
        x[0][0] = alpha*s00 + beta*a00 + gamma;
        x[0][1] = alpha*s01 + beta*a01;         x[1][0] = x[0][1];
        x[0][2] = alpha*s02 + beta*a02;         x[2][0] = x[0][2];
        x[1][1] = alpha*s11 + beta*a11 + gamma;
        x[1][2] = alpha*s12 + beta*a12;         x[2][1] = x[1][2];
        x[2][2] = alpha*s22 + beta*a22 + gamma;

        // Y = M * X3   [9,3]  (M in registers)
        float Y[9][3];
        #pragma unroll
        for (int rr = 0; rr < 9; rr++) {
            const float m0 = M[rr*3+0], m1 = M[rr*3+1], m2 = M[rr*3+2];
            #pragma unroll
            for (int k = 0; k < 3; k++)
                Y[rr][k] = m0 * x[0][k] + m1 * x[1][k] + m2 * x[2][k];
        }

        // X9 = Y * M^T + C9 (symmetric) -> own slice
        float* st = &slice[lane * 81];
        #pragma unroll
        for (int rr = 0; rr < 9; rr++) {
            #pragma unroll
            for (int cc = rr; cc < 9; cc++) {
                const float val = Y[rr][0] * M[cc*3+0]
                                + Y[rr][1] * M[cc*3+1]
                                + Y[rr][2] * M[cc*3+2]
                                + sC[rr*9+cc];
                st[rr*9+cc] = val;
                st[cc*9+rr] = val;
            }
        }
    }
    __syncwarp();

    // Coalesced copy of this warp's slice (2592 floats = 648 float4)
    if (wn == 32) {
        float4* o4 = reinterpret_cast<float4*>(out + (size_t)wItem0 * 81);
        const float4* s4 = reinterpret_cast<const float4*>(slice);
        #pragma unroll 4
        for (int idx = lane; idx < (32 * 81) / 4; idx += 32)
            o4[idx] = s4[idx];
    } else if (wn > 0) {
        float* ob = out + (size_t)wItem0 * 81;
        for (int idx = lane; idx < wn * 81; idx += 32)
            ob[idx] = slice[idx];
    }
}

// ---------------------------------------------------------------------------
extern "C" void kernel_launch(void* const* d_in, const int* in_sizes, int n_in,
                              void* d_out, int out_size) {
    const float* vech = nullptr;
    const float* W1 = nullptr;
    const float* W2 = nullptr;
    const float* W3 = nullptr;
    int vech_elems = 0;
    for (int i = 0; i < n_in; i++) {
        int sz = in_sizes[i];
        if (sz == 15)      W1 = (const float*)d_in[i];
        else if (sz == 35) W2 = (const float*)d_in[i];
        else if (sz == 63) W3 = (const float*)d_in[i];
        else { vech = (const float*)d_in[i]; vech_elems = sz; }
    }
    int B = vech_elems / 6;
    int grid = (B + BLK - 1) / BLK;
    spd_main_kernel<<<grid, BLK>>>(vech, W1, W2, W3, (float*)d_out, B);
}